// round 15
// baseline (speedup 1.0000x reference)
#include <cuda_runtime.h>
#include <cuda_bf16.h>
#include <cstdint>

#define NCONCEPTS 4096
#define CDIM      1024
#define BATCH     4096
#define KSAMP     256
#define ROWS_PER_BLOCK 4
#define NBLK (BATCH / ROWS_PER_BLOCK)   // 1024 blocks -> ~7/SM, one wave

// Scratch for per-concept dot products (no cudaMalloc allowed).
__device__ float g_s[NCONCEPTS];

// Kernel 1: one warp per concept row: s[c] = sum_d cb[c,d] * A[c,d]
__global__ void __launch_bounds__(256) dot_rows_kernel(
    const float* __restrict__ cb,
    const float* __restrict__ at)
{
    const int row  = blockIdx.x * 8 + (threadIdx.x >> 5);
    const int lane = threadIdx.x & 31;

    const float4* __restrict__ a = reinterpret_cast<const float4*>(cb + (size_t)row * CDIM);
    const float4* __restrict__ b = reinterpret_cast<const float4*>(at + (size_t)row * CDIM);

    float acc = 0.0f;
#pragma unroll
    for (int i = 0; i < CDIM / 4 / 32; ++i) {   // 8 iterations
        float4 x = a[lane + i * 32];
        float4 y = b[lane + i * 32];
        acc += x.x * y.x + x.y * y.y + x.z * y.z + x.w * y.w;
    }
#pragma unroll
    for (int off = 16; off > 0; off >>= 1)
        acc += __shfl_xor_sync(0xffffffffu, acc, off);

    if (lane == 0)
        g_s[row] = acc;
}

// Kernel 2: 1024 blocks, 4 rows each, double-buffered smem row staging.
// Iteration i: phase X zeroes buf[i&1] AND copies out buf[(i-1)&1]
// (different buffers, one barrier), phase Y scatters into buf[i&1] and
// prefetches the next row's idx -> g_s dependent chain.
// All global stores are full-line coalesced float4; randomness stays in smem.
// sampled_idx is int32 on-device (JAX default x32 downcasts the int64 request).
// Duplicate indices write the same value -> benign.
__global__ void __launch_bounds__(256) row_build_kernel(
    const int* __restrict__ idx,
    float* __restrict__ out)
{
    __shared__ float buf[2][NCONCEPTS];

    const int t    = threadIdx.x;
    const int base = blockIdx.x * ROWS_PER_BLOCK;

    // Prefetch row 0's dependent chain.
    int   c = idx[(size_t)base * KSAMP + t];
    float v = g_s[c];

    const float4 z = make_float4(0.f, 0.f, 0.f, 0.f);

#pragma unroll
    for (int i = 0; i < ROWS_PER_BLOCK; ++i) {
        float4* __restrict__ sb = reinterpret_cast<float4*>(buf[i & 1]);

        // Phase X: zero current buffer; copy out previous buffer.
#pragma unroll
        for (int j = 0; j < NCONCEPTS / 4 / 256; ++j)   // 4 iters
            sb[t + j * 256] = z;

        if (i > 0) {
            const float4* __restrict__ sp = reinterpret_cast<const float4*>(buf[(i - 1) & 1]);
            float4* __restrict__ o4 =
                reinterpret_cast<float4*>(out + (size_t)(base + i - 1) * NCONCEPTS);
#pragma unroll
            for (int j = 0; j < NCONCEPTS / 4 / 256; ++j)
                o4[t + j * 256] = sp[t + j * 256];
        }
        __syncthreads();

        // Phase Y: scatter into current buffer; prefetch next row's chain.
        buf[i & 1][c] = v;
        if (i + 1 < ROWS_PER_BLOCK) {
            c = idx[(size_t)(base + i + 1) * KSAMP + t];
            v = g_s[c];
        }
        __syncthreads();
    }

    // Final copy-out of the last row.
    {
        const float4* __restrict__ sp =
            reinterpret_cast<const float4*>(buf[(ROWS_PER_BLOCK - 1) & 1]);
        float4* __restrict__ o4 =
            reinterpret_cast<float4*>(out + (size_t)(base + ROWS_PER_BLOCK - 1) * NCONCEPTS);
#pragma unroll
        for (int j = 0; j < NCONCEPTS / 4 / 256; ++j)
            o4[t + j * 256] = sp[t + j * 256];
    }
}

extern "C" void kernel_launch(void* const* d_in, const int* in_sizes, int n_in,
                              void* d_out, int out_size)
{
    const float* cb  = (const float*)d_in[0];
    const float* at  = (const float*)d_in[1];
    const int*   idx = (const int*)d_in[2];
    float*       out = (float*)d_out;

    dot_rows_kernel<<<NCONCEPTS / 8, 256>>>(cb, at);
    row_build_kernel<<<NBLK, 256>>>(idx, out);
}